// round 2
// baseline (speedup 1.0000x reference)
#include <cuda_runtime.h>
#include <math.h>

#define B_ 8
#define E_ 2048
#define H_ 16
#define HD_ 128
#define LOW_ 512
#define SPREV_ 4095
#define S_ 4096
#define KS_ 64           // k-splits for the 2048-deep small GEMMs
#define KCH_ 32          // 2048 / 64
#define SPLITS_ 16       // attention sequence splits
#define CHUNK_ 256       // 4096 / 16
#define TS_ 16           // rows per attention tile

// ---------------- scratch (static device memory; no allocations) ----------------
__device__ float g_Cq[B_*E_];
__device__ float g_Qc[B_*E_];
__device__ float g_qr_pre[B_*HD_];
__device__ float g_qr[B_*HD_];
__device__ float g_qabs[B_*H_*LOW_];
__device__ float g_ckv_new[B_*LOW_];
__device__ float g_kr_new[B_*HD_];
__device__ float g_cos[S_*64];
__device__ float g_sin[S_*64];
__device__ float g_scr[B_*S_];
__device__ float g_part[KS_*B_*E_];
__device__ float g_m[B_*H_*SPLITS_];
__device__ float g_l[B_*H_*SPLITS_];
__device__ float g_ctxp[B_*H_*SPLITS_*LOW_];
__device__ float g_ctxf[B_*H_*LOW_];
__device__ float g_opart[8*B_*H_*HD_];
__device__ float g_o[B_*E_];

// ---------------- rope table: cos/sin of fp32-rounded angle --------------------
__global__ void k_rope() {
    int idx = blockIdx.x * blockDim.x + threadIdx.x;
    if (idx >= S_ * 64) return;
    int s = idx >> 6, i = idx & 63;
    float invf = (float)(1.0 / pow(10000.0, (double)i / 64.0));
    float ang = (float)s * invf;              // fp32 round, like jnp
    double sn, c;
    sincos((double)ang, &sn, &c);
    g_cos[idx] = (float)c;
    g_sin[idx] = (float)sn;
}

// ---------------- generic M=8 GEMM, k-split partials ---------------------------
// Out[b,n] = sum_k X[b,k] * W[k,n], K=2048. grid (ceil(N/256), KS_), 256 thr.
__global__ void k_gemm8(const float* __restrict__ X, const float* __restrict__ W,
                        float* __restrict__ part, int N) {
    __shared__ float xs[B_][KCH_];
    int tid = threadIdx.x;
    int k0 = blockIdx.y * KCH_;
    {
        int b = tid >> 5, kk = tid & 31;   // 256 = 8*32
        xs[b][kk] = X[b * E_ + k0 + kk];
    }
    __syncthreads();
    int n = blockIdx.x * 256 + tid;
    if (n < N) {
        float acc[B_] = {0.f,0.f,0.f,0.f,0.f,0.f,0.f,0.f};
        const float* wp = W + (size_t)k0 * N + n;
        #pragma unroll
        for (int kk = 0; kk < KCH_; ++kk) {
            float wv = wp[(size_t)kk * N];
            #pragma unroll
            for (int b = 0; b < B_; ++b) acc[b] = fmaf(xs[b][kk], wv, acc[b]);
        }
        float* pp = part + (size_t)(blockIdx.y * B_) * N + n;
        #pragma unroll
        for (int b = 0; b < B_; ++b) pp[(size_t)b * N] = acc[b];
    }
}

__global__ void k_reduce8(const float* __restrict__ part, float* __restrict__ out, int N) {
    int idx = blockIdx.x * 256 + threadIdx.x;
    if (idx >= B_ * N) return;
    int b = idx / N, n = idx - b * N;
    float acc = 0.f;
    #pragma unroll 8
    for (int s = 0; s < KS_; ++s) acc += part[(size_t)(s * B_ + b) * N + n];
    out[idx] = acc;
}

// ---------------- rope the query rotary part at position S-1 -------------------
__global__ void k_ropeq() {
    int b = blockIdx.x, i = threadIdx.x;   // 64 threads
    float q1 = g_qr_pre[b * HD_ + i];
    float q2 = g_qr_pre[b * HD_ + i + 64];
    float c = g_cos[(S_ - 1) * 64 + i];
    float s = g_sin[(S_ - 1) * 64 + i];
    g_qr[b * HD_ + i]       = q1 * c - q2 * s;
    g_qr[b * HD_ + i + 64]  = q1 * s + q2 * c;
}

// ---------------- absorbed query: q_abs[b,h,low] = Qc[b,h,:] . Wuk[low,h,:] ----
__global__ void k_qabs(const float* __restrict__ FU) {
    int h = blockIdx.y;
    int w = threadIdx.x >> 5, lane = threadIdx.x & 31;
    int low = blockIdx.x * 8 + w;
    float4 w4 = *(const float4*)(FU + (size_t)low * (2 * E_) + h * HD_ + lane * 4);
    #pragma unroll
    for (int b = 0; b < B_; ++b) {
        float4 q4 = *(const float4*)(g_Qc + b * E_ + h * HD_ + lane * 4);
        float acc = w4.x * q4.x + w4.y * q4.y + w4.z * q4.z + w4.w * q4.w;
        #pragma unroll
        for (int off = 16; off; off >>= 1) acc += __shfl_xor_sync(0xffffffffu, acc, off);
        if (lane == 0) g_qabs[(b * H_ + h) * LOW_ + low] = acc;
    }
}

// ---------------- rotary scores: scr[b,s] = rope(kr[b,s],s) . qr_roped[b] ------
__global__ void k_scr(const float* __restrict__ krc) {
    int gw = blockIdx.x * 8 + (threadIdx.x >> 5);
    int lane = threadIdx.x & 31;
    int b = gw >> 12;
    int s = gw & (S_ - 1);
    const float* kr = (s < SPREV_) ? (krc + ((size_t)b * SPREV_ + s) * HD_)
                                   : (g_kr_new + b * HD_);
    float k1a = kr[lane], k1b = kr[lane + 32], k2a = kr[lane + 64], k2b = kr[lane + 96];
    float ca = g_cos[s * 64 + lane], cb = g_cos[s * 64 + lane + 32];
    float sa = g_sin[s * 64 + lane], sb = g_sin[s * 64 + lane + 32];
    const float* q = g_qr + b * HD_;
    float q1a = q[lane], q1b = q[lane + 32], q2a = q[lane + 64], q2b = q[lane + 96];
    float acc = ca * (q1a * k1a + q2a * k2a) + sa * (q2a * k1a - q1a * k2a)
              + cb * (q1b * k1b + q2b * k2b) + sb * (q2b * k1b - q1b * k2b);
    #pragma unroll
    for (int off = 16; off; off >>= 1) acc += __shfl_xor_sync(0xffffffffu, acc, off);
    if (lane == 0) g_scr[b * S_ + s] = acc;
}

// ---------------- flash attention in latent space ------------------------------
// grid (SPLITS_, B_), 512 threads. warp w = head w (scores); thread t = low t (ctx).
__global__ void __launch_bounds__(512, 1) k_attn(const float* __restrict__ ckv) {
    __shared__ float cvs[TS_][LOW_];
    __shared__ float p_s[H_][TS_];
    __shared__ float alpha_s[H_];
    int split = blockIdx.x, b = blockIdx.y;
    int tid = threadIdx.x, w = tid >> 5, lane = tid & 31;

    float q[16];
    {
        const float* qa = g_qabs + (b * H_ + w) * LOW_;
        #pragma unroll
        for (int g = 0; g < 4; ++g) {
            float4 t = *(const float4*)(qa + g * 128 + lane * 4);
            q[g * 4 + 0] = t.x; q[g * 4 + 1] = t.y;
            q[g * 4 + 2] = t.z; q[g * 4 + 3] = t.w;
        }
    }
    float m = -1e30f, l = 0.f;
    float ctx[16];
    #pragma unroll
    for (int h = 0; h < H_; ++h) ctx[h] = 0.f;

    int s0 = split * CHUNK_;
    for (int tile = 0; tile < CHUNK_ / TS_; ++tile) {
        int sb = s0 + tile * TS_;
        __syncthreads();   // protect cvs/p_s reuse from previous tile
        #pragma unroll
        for (int i = 0; i < 4; ++i) {
            int g = tid + 512 * i;
            int r = g >> 7;
            int c4 = (g & 127) << 2;
            int sidx = sb + r;
            const float* src = (sidx < SPREV_)
                ? (ckv + ((size_t)b * SPREV_ + sidx) * LOW_ + c4)
                : (g_ckv_new + b * LOW_ + c4);
            *(float4*)&cvs[r][c4] = *(const float4*)src;
        }
        __syncthreads();

        // ---- scores for head w (one warp per head) ----
        float p[TS_];
        {
            float sc[TS_];
            #pragma unroll
            for (int r = 0; r < TS_; ++r) {
                float acc = 0.f;
                #pragma unroll
                for (int g = 0; g < 4; ++g) {
                    float4 c = *(const float4*)&cvs[r][g * 128 + lane * 4];
                    acc = fmaf(q[g * 4 + 0], c.x, acc);
                    acc = fmaf(q[g * 4 + 1], c.y, acc);
                    acc = fmaf(q[g * 4 + 2], c.z, acc);
                    acc = fmaf(q[g * 4 + 3], c.w, acc);
                }
                #pragma unroll
                for (int off = 16; off; off >>= 1) acc += __shfl_xor_sync(0xffffffffu, acc, off);
                sc[r] = acc;
            }
            float mt = -1e30f;
            #pragma unroll
            for (int r = 0; r < TS_; ++r) {
                sc[r] = (sc[r] + g_scr[b * S_ + sb + r]) * 0.0625f;  // / sqrt(256)
                mt = fmaxf(mt, sc[r]);
            }
            float mn = fmaxf(m, mt);
            float al = __expf(m - mn);
            float ps = 0.f;
            #pragma unroll
            for (int r = 0; r < TS_; ++r) { p[r] = __expf(sc[r] - mn); ps += p[r]; }
            l = l * al + ps;
            m = mn;
            if (lane == 0) {
                alpha_s[w] = al;
                #pragma unroll
                for (int r = 0; r < TS_; ++r) p_s[w][r] = p[r];
            }
        }
        __syncthreads();

        // ---- ctx update: thread owns low = tid, accumulates all 16 heads ----
        float cv[TS_];
        #pragma unroll
        for (int r = 0; r < TS_; ++r) cv[r] = cvs[r][tid];
        #pragma unroll
        for (int h = 0; h < H_; ++h) {
            float c = ctx[h] * alpha_s[h];
            #pragma unroll
            for (int r = 0; r < TS_; ++r) c = fmaf(p_s[h][r], cv[r], c);
            ctx[h] = c;
        }
    }

    #pragma unroll
    for (int h = 0; h < H_; ++h)
        g_ctxp[(size_t)((b * H_ + h) * SPLITS_ + split) * LOW_ + tid] = ctx[h];
    if (lane == 0) {
        g_m[(b * H_ + w) * SPLITS_ + split] = m;
        g_l[(b * H_ + w) * SPLITS_ + split] = l;
    }
}

// ---------------- combine split partials + normalize ---------------------------
__global__ void k_combine() {
    int bh = blockIdx.x;        // 128
    int tid = threadIdx.x;      // 512
    float mg = -1e30f;
    #pragma unroll
    for (int s = 0; s < SPLITS_; ++s) mg = fmaxf(mg, g_m[bh * SPLITS_ + s]);
    float L = 0.f, acc = 0.f;
    #pragma unroll
    for (int s = 0; s < SPLITS_; ++s) {
        float wgt = __expf(g_m[bh * SPLITS_ + s] - mg);
        L += g_l[bh * SPLITS_ + s] * wgt;
        acc += g_ctxp[(size_t)(bh * SPLITS_ + s) * LOW_ + tid] * wgt;
    }
    g_ctxf[bh * LOW_ + tid] = acc / L;
}

// ---------------- V projection: o[b,h,d] = ctxf[b,h,:] . Wv[:,h,d] -------------
__global__ void k_vproj(const float* __restrict__ FU) {
    int h = blockIdx.x, ls = blockIdx.y;   // 16 x 8
    int d = threadIdx.x;                   // 128
    __shared__ float cf[B_][64];
    #pragma unroll
    for (int j = 0; j < 4; ++j) {
        int i = d + 128 * j;
        int bb = i >> 6, lo = i & 63;
        cf[bb][lo] = g_ctxf[(bb * H_ + h) * LOW_ + ls * 64 + lo];
    }
    __syncthreads();
    float acc[B_] = {0.f,0.f,0.f,0.f,0.f,0.f,0.f,0.f};
    #pragma unroll 8
    for (int lo = 0; lo < 64; ++lo) {
        float wv = FU[(size_t)(ls * 64 + lo) * (2 * E_) + E_ + h * HD_ + d];
        #pragma unroll
        for (int b = 0; b < B_; ++b) acc[b] = fmaf(cf[b][lo], wv, acc[b]);
    }
    #pragma unroll
    for (int b = 0; b < B_; ++b)
        g_opart[((ls * B_ + b) * H_ + h) * HD_ + d] = acc[b];
}

__global__ void k_reduceo() {
    int idx = blockIdx.x * 256 + threadIdx.x;
    if (idx >= B_ * E_) return;
    int b = idx >> 11, e = idx & 2047;
    int h = e >> 7, d = e & 127;
    float acc = 0.f;
    #pragma unroll
    for (int ls = 0; ls < 8; ++ls)
        acc += g_opart[((ls * B_ + b) * H_ + h) * HD_ + d];
    g_o[idx] = acc;
}

// -------------------------------------------------------------------------------
extern "C" void kernel_launch(void* const* d_in, const int* in_sizes, int n_in,
                              void* d_out, int out_size) {
    const float* x    = (const float*)d_in[0];
    const float* ckv  = (const float*)d_in[1];
    const float* krc  = (const float*)d_in[2];
    const float* Wdq  = (const float*)d_in[3];
    const float* Wuq  = (const float*)d_in[4];
    const float* Wqr  = (const float*)d_in[5];
    const float* Wdkv = (const float*)d_in[6];
    const float* Wkr  = (const float*)d_in[7];
    const float* FU   = (const float*)d_in[8];
    const float* Wo   = (const float*)d_in[9];
    float* out = (float*)d_out;

    float *pCq, *pQc, *pPart, *pQrp, *pCkvn, *pKrn, *pO;
    cudaGetSymbolAddress((void**)&pCq,   g_Cq);
    cudaGetSymbolAddress((void**)&pQc,   g_Qc);
    cudaGetSymbolAddress((void**)&pPart, g_part);
    cudaGetSymbolAddress((void**)&pQrp,  g_qr_pre);
    cudaGetSymbolAddress((void**)&pCkvn, g_ckv_new);
    cudaGetSymbolAddress((void**)&pKrn,  g_kr_new);
    cudaGetSymbolAddress((void**)&pO,    g_o);

    k_rope<<<(S_ * 64) / 256, 256>>>();

    // Cq = x @ Wdq
    k_gemm8<<<dim3(8, KS_), 256>>>(x, Wdq, pPart, E_);
    k_reduce8<<<(B_ * E_ + 255) / 256, 256>>>(pPart, pCq, E_);
    // ckv_new = x @ Wdkv
    k_gemm8<<<dim3(2, KS_), 256>>>(x, Wdkv, pPart, LOW_);
    k_reduce8<<<(B_ * LOW_ + 255) / 256, 256>>>(pPart, pCkvn, LOW_);
    // kr_new = x @ Wkr
    k_gemm8<<<dim3(1, KS_), 256>>>(x, Wkr, pPart, HD_);
    k_reduce8<<<(B_ * HD_ + 255) / 256, 256>>>(pPart, pKrn, HD_);
    // Qc = Cq @ Wuq
    k_gemm8<<<dim3(8, KS_), 256>>>(pCq, Wuq, pPart, E_);
    k_reduce8<<<(B_ * E_ + 255) / 256, 256>>>(pPart, pQc, E_);
    // qr_pre = Cq @ Wqr ; rope at pos S-1
    k_gemm8<<<dim3(1, KS_), 256>>>(pCq, Wqr, pPart, HD_);
    k_reduce8<<<(B_ * HD_ + 255) / 256, 256>>>(pPart, pQrp, HD_);
    k_ropeq<<<B_, 64>>>();

    k_qabs<<<dim3(64, 16), 256>>>(FU);
    k_scr<<<4096, 256>>>(krc);
    k_attn<<<dim3(SPLITS_, B_), 512>>>(ckv);
    k_combine<<<128, 512>>>();
    k_vproj<<<dim3(16, 8), 128>>>(FU);
    k_reduceo<<<(B_ * E_ + 255) / 256, 256>>>();

    // out = o @ Wo
    k_gemm8<<<dim3(8, KS_), 256>>>(pO, Wo, pPart, E_);
    k_reduce8<<<(B_ * E_ + 255) / 256, 256>>>(pPart, out, E_);
    (void)in_sizes; (void)n_in; (void)out_size;
}

// round 3
// speedup vs baseline: 1.2822x; 1.2822x over previous
#include <cuda_runtime.h>
#include <math.h>

#define B_ 8
#define E_ 2048
#define H_ 16
#define HD_ 128
#define LOW_ 512
#define SPREV_ 4095
#define S_ 4096
#define KS_ 64
#define KC2_ 32
#define SPLITS_ 16
#define CHUNK_ 256
#define TS_ 16
#define NT_ (CHUNK_ / TS_)

__device__ float g_Cq[B_*E_];
__device__ float g_Qc[B_*E_];
__device__ float g_qr_pre[B_*HD_];
__device__ float g_qr[B_*HD_];
__device__ float g_qabs[B_*H_*LOW_];
__device__ float g_ckv_new[B_*LOW_];
__device__ float g_kr_new[B_*HD_];
__device__ float g_invf[64];
__device__ float g_cos[S_*64];
__device__ float g_sin[S_*64];
__device__ float g_scr[B_*S_];
__device__ float g_part[KS_*B_*E_];
__device__ float g_m[B_*H_*SPLITS_];
__device__ float g_l[B_*H_*SPLITS_];
__device__ float g_ctxp[B_*H_*SPLITS_*LOW_];
__device__ float g_ctxf[B_*H_*LOW_];
__device__ float g_opart[8*B_*H_*HD_];
__device__ float g_o[B_*E_];

__device__ __forceinline__ void fma2(float2& c, float2 a, float2 b) {
    unsigned long long C, A, Bv;
    C = *reinterpret_cast<unsigned long long*>(&c);
    A = *reinterpret_cast<unsigned long long*>(&a);
    Bv = *reinterpret_cast<unsigned long long*>(&b);
    asm("fma.rn.f32x2 %0, %1, %2, %0;" : "+l"(C) : "l"(A), "l"(Bv));
    c = *reinterpret_cast<float2*>(&C);
}

// ---------------- rope tables ---------------------------------------------------
__global__ void k_invf() {
    int i = threadIdx.x;  // 64
    g_invf[i] = (float)(1.0 / pow(10000.0, (double)i / 64.0));
}
__global__ void k_rope() {
    int idx = blockIdx.x * blockDim.x + threadIdx.x;
    if (idx >= S_ * 64) return;
    int s = idx >> 6, i = idx & 63;
    float ang = (float)s * g_invf[i];    // fp32 round like jnp
    float sn, c;
    sincosf(ang, &sn, &c);
    g_cos[idx] = c;
    g_sin[idx] = sn;
}

// ---------------- M=8 GEMM v2: float4 streaming, k-split ------------------------
__global__ void __launch_bounds__(256) k_gemm8v(const float* __restrict__ X,
        const float* __restrict__ W, float* __restrict__ part, int N) {
    __shared__ float xs[B_][KC2_];
    int tid = threadIdx.x;
    int k0 = blockIdx.y * KC2_;
    for (int i = tid; i < B_ * KC2_; i += blockDim.x) {
        int bb = i >> 5, kk = i & 31;
        xs[bb][kk] = X[bb * E_ + k0 + kk];
    }
    __syncthreads();
    int N4 = N >> 2;
    int n4 = blockIdx.x * blockDim.x + tid;
    if (n4 >= N4) return;
    const float4* Wp = (const float4*)W + (size_t)k0 * N4 + n4;
    float4 acc[B_];
    #pragma unroll
    for (int b = 0; b < B_; ++b) acc[b] = make_float4(0.f, 0.f, 0.f, 0.f);
    #pragma unroll
    for (int kk = 0; kk < KC2_; ++kk) {
        float4 w4 = Wp[(size_t)kk * N4];
        #pragma unroll
        for (int b = 0; b < B_; ++b) {
            float xv = xs[b][kk];
            acc[b].x = fmaf(xv, w4.x, acc[b].x);
            acc[b].y = fmaf(xv, w4.y, acc[b].y);
            acc[b].z = fmaf(xv, w4.z, acc[b].z);
            acc[b].w = fmaf(xv, w4.w, acc[b].w);
        }
    }
    float4* pp = (float4*)part + (size_t)(blockIdx.y * B_) * N4 + n4;
    #pragma unroll
    for (int b = 0; b < B_; ++b) pp[(size_t)b * N4] = acc[b];
}

__global__ void k_reduce8(const float* __restrict__ part, float* __restrict__ out, int N) {
    int idx = blockIdx.x * 256 + threadIdx.x;
    if (idx >= B_ * N) return;
    float acc = 0.f;
    #pragma unroll 8
    for (int s = 0; s < KS_; ++s) acc += part[(size_t)s * (B_ * N) + idx];
    out[idx] = acc;
}

// ---------------- rope query at pos S-1 -----------------------------------------
__global__ void k_ropeq() {
    int b = blockIdx.x, i = threadIdx.x;   // 64
    float q1 = g_qr_pre[b * HD_ + i];
    float q2 = g_qr_pre[b * HD_ + i + 64];
    float c = g_cos[(S_ - 1) * 64 + i];
    float s = g_sin[(S_ - 1) * 64 + i];
    g_qr[b * HD_ + i]      = q1 * c - q2 * s;
    g_qr[b * HD_ + i + 64] = q1 * s + q2 * c;
}

// ---------------- absorbed query ------------------------------------------------
__global__ void k_qabs(const float* __restrict__ FU) {
    int h = blockIdx.y;
    int w = threadIdx.x >> 5, lane = threadIdx.x & 31;
    int low = blockIdx.x * 8 + w;
    float4 w4 = *(const float4*)(FU + (size_t)low * (2 * E_) + h * HD_ + lane * 4);
    #pragma unroll
    for (int b = 0; b < B_; ++b) {
        float4 q4 = *(const float4*)(g_Qc + b * E_ + h * HD_ + lane * 4);
        float acc = w4.x * q4.x + w4.y * q4.y + w4.z * q4.z + w4.w * q4.w;
        #pragma unroll
        for (int off = 16; off; off >>= 1) acc += __shfl_xor_sync(0xffffffffu, acc, off);
        if (lane == 0) g_qabs[(b * H_ + h) * LOW_ + low] = acc;
    }
}

// ---------------- rotary scores -------------------------------------------------
__global__ void k_scr(const float* __restrict__ krc) {
    int gw = blockIdx.x * 8 + (threadIdx.x >> 5);
    int lane = threadIdx.x & 31;
    int b = gw >> 12;
    int s = gw & (S_ - 1);
    const float* kr = (s < SPREV_) ? (krc + ((size_t)b * SPREV_ + s) * HD_)
                                   : (g_kr_new + b * HD_);
    float k1a = kr[lane], k1b = kr[lane + 32], k2a = kr[lane + 64], k2b = kr[lane + 96];
    float ca = g_cos[s * 64 + lane], cb = g_cos[s * 64 + lane + 32];
    float sa = g_sin[s * 64 + lane], sb = g_sin[s * 64 + lane + 32];
    const float* q = g_qr + b * HD_;
    float q1a = q[lane], q1b = q[lane + 32], q2a = q[lane + 64], q2b = q[lane + 96];
    float acc = ca * (q1a * k1a + q2a * k2a) + sa * (q2a * k1a - q1a * k2a)
              + cb * (q1b * k1b + q2b * k2b) + sb * (q2b * k1b - q1b * k2b);
    #pragma unroll
    for (int off = 16; off; off >>= 1) acc += __shfl_xor_sync(0xffffffffu, acc, off);
    if (lane == 0) g_scr[b * S_ + s] = acc;
}

// ---------------- flash attention v2: prefetch + f32x2 --------------------------
__global__ void __launch_bounds__(512, 1) k_attn(const float* __restrict__ ckv) {
    __shared__ float cvs[TS_][LOW_];     // 32 KB
    __shared__ float p_s[TS_][20];       // probs [row][head], pad 20
    __shared__ float alpha_s[20];
    __shared__ float scs[CHUNK_];
    int split = blockIdx.x, b = blockIdx.y;
    int tid = threadIdx.x, w = tid >> 5, lane = tid & 31;
    int s0 = split * CHUNK_;

    if (tid < CHUNK_) scs[tid] = g_scr[b * S_ + s0 + tid];

    // q packed as f32x2 pairs
    float2 q2[8];
    {
        const float* qa = g_qabs + (b * H_ + w) * LOW_;
        #pragma unroll
        for (int g = 0; g < 4; ++g) {
            float4 t = *(const float4*)(qa + g * 128 + lane * 4);
            q2[2 * g]     = make_float2(t.x, t.y);
            q2[2 * g + 1] = make_float2(t.z, t.w);
        }
    }
    float m = -1e30f, l = 0.f;
    float2 ctx2[8];
    #pragma unroll
    for (int hp = 0; hp < 8; ++hp) ctx2[hp] = make_float2(0.f, 0.f);

    int ldr = tid >> 7;               // row this thread loads (4 rows per pass)
    int ldc = (tid & 127) << 2;       // float4 column
    float4 pf[4];

    // prologue: tile 0
    #pragma unroll
    for (int i = 0; i < 4; ++i) {
        int sidx = s0 + ldr + 4 * i;
        const float* src = (sidx < SPREV_)
            ? (ckv + ((size_t)b * SPREV_ + sidx) * LOW_ + ldc)
            : (g_ckv_new + b * LOW_ + ldc);
        pf[i] = *(const float4*)src;
    }
    #pragma unroll
    for (int i = 0; i < 4; ++i) *(float4*)&cvs[ldr + 4 * i][ldc] = pf[i];
    __syncthreads();

    for (int tile = 0; tile < NT_; ++tile) {
        int sb = s0 + tile * TS_;
        // prefetch next tile into regs (overlaps with compute)
        if (tile + 1 < NT_) {
            #pragma unroll
            for (int i = 0; i < 4; ++i) {
                int sidx = sb + TS_ + ldr + 4 * i;
                const float* src = (sidx < SPREV_)
                    ? (ckv + ((size_t)b * SPREV_ + sidx) * LOW_ + ldc)
                    : (g_ckv_new + b * LOW_ + ldc);
                pf[i] = *(const float4*)src;
            }
        }

        // ---- scores: warp w = head w ----
        float sc[TS_];
        #pragma unroll
        for (int r = 0; r < TS_; ++r) {
            float2 a2 = make_float2(0.f, 0.f);
            #pragma unroll
            for (int g = 0; g < 4; ++g) {
                float4 c = *(const float4*)&cvs[r][g * 128 + lane * 4];
                fma2(a2, make_float2(c.x, c.y), q2[2 * g]);
                fma2(a2, make_float2(c.z, c.w), q2[2 * g + 1]);
            }
            float acc = a2.x + a2.y;
            #pragma unroll
            for (int off = 16; off; off >>= 1) acc += __shfl_xor_sync(0xffffffffu, acc, off);
            sc[r] = acc;
        }
        float mt = -1e30f;
        #pragma unroll
        for (int r = 0; r < TS_; ++r) {
            sc[r] = (sc[r] + scs[tile * TS_ + r]) * 0.0625f;
            mt = fmaxf(mt, sc[r]);
        }
        float mn = fmaxf(m, mt);
        float al = __expf(m - mn);
        float ps = 0.f;
        float p[TS_];
        #pragma unroll
        for (int r = 0; r < TS_; ++r) { p[r] = __expf(sc[r] - mn); ps += p[r]; }
        l = l * al + ps;
        m = mn;
        if (lane == 0) {
            alpha_s[w] = al;
            #pragma unroll
            for (int r = 0; r < TS_; ++r) p_s[r][w] = p[r];
        }
        __syncthreads();

        // ---- ctx: thread owns low=tid, f32x2 over head pairs ----
        float cv[TS_];
        #pragma unroll
        for (int r = 0; r < TS_; ++r) cv[r] = cvs[r][tid];
        #pragma unroll
        for (int hp = 0; hp < 8; ++hp) {
            float2 alp = *(const float2*)&alpha_s[2 * hp];
            ctx2[hp].x *= alp.x;
            ctx2[hp].y *= alp.y;
        }
        #pragma unroll
        for (int r = 0; r < TS_; ++r) {
            float2 cvr = make_float2(cv[r], cv[r]);
            #pragma unroll
            for (int g = 0; g < 4; ++g) {
                float4 pq = *(const float4*)&p_s[r][4 * g];
                fma2(ctx2[2 * g],     cvr, make_float2(pq.x, pq.y));
                fma2(ctx2[2 * g + 1], cvr, make_float2(pq.z, pq.w));
            }
        }
        __syncthreads();

        // store prefetched tile
        if (tile + 1 < NT_) {
            #pragma unroll
            for (int i = 0; i < 4; ++i) *(float4*)&cvs[ldr + 4 * i][ldc] = pf[i];
            __syncthreads();
        }
    }

    #pragma unroll
    for (int hp = 0; hp < 8; ++hp) {
        g_ctxp[(size_t)((b * H_ + 2 * hp)     * SPLITS_ + split) * LOW_ + tid] = ctx2[hp].x;
        g_ctxp[(size_t)((b * H_ + 2 * hp + 1) * SPLITS_ + split) * LOW_ + tid] = ctx2[hp].y;
    }
    if (lane == 0) {
        g_m[(b * H_ + w) * SPLITS_ + split] = m;
        g_l[(b * H_ + w) * SPLITS_ + split] = l;
    }
}

// ---------------- combine split partials ----------------------------------------
__global__ void k_combine() {
    int bh = blockIdx.x;        // 128
    int tid = threadIdx.x;      // 512
    float mg = -1e30f;
    #pragma unroll
    for (int s = 0; s < SPLITS_; ++s) mg = fmaxf(mg, g_m[bh * SPLITS_ + s]);
    float L = 0.f, acc = 0.f;
    #pragma unroll
    for (int s = 0; s < SPLITS_; ++s) {
        float wgt = __expf(g_m[bh * SPLITS_ + s] - mg);
        L += g_l[bh * SPLITS_ + s] * wgt;
        acc += g_ctxp[(size_t)(bh * SPLITS_ + s) * LOW_ + tid] * wgt;
    }
    g_ctxf[bh * LOW_ + tid] = acc / L;
}

// ---------------- V projection --------------------------------------------------
__global__ void k_vproj(const float* __restrict__ FU) {
    int h = blockIdx.x, ls = blockIdx.y;   // 16 x 8
    int d = threadIdx.x;                   // 128
    __shared__ float cf[B_][64];
    #pragma unroll
    for (int j = 0; j < 4; ++j) {
        int i = d + 128 * j;
        int bb = i >> 6, lo = i & 63;
        cf[bb][lo] = g_ctxf[(bb * H_ + h) * LOW_ + ls * 64 + lo];
    }
    __syncthreads();
    float acc[B_] = {0.f,0.f,0.f,0.f,0.f,0.f,0.f,0.f};
    #pragma unroll 8
    for (int lo = 0; lo < 64; ++lo) {
        float wv = FU[(size_t)(ls * 64 + lo) * (2 * E_) + E_ + h * HD_ + d];
        #pragma unroll
        for (int b = 0; b < B_; ++b) acc[b] = fmaf(cf[b][lo], wv, acc[b]);
    }
    #pragma unroll
    for (int b = 0; b < B_; ++b)
        g_opart[((ls * B_ + b) * H_ + h) * HD_ + d] = acc[b];
}

__global__ void k_reduceo() {
    int idx = blockIdx.x * 256 + threadIdx.x;
    if (idx >= B_ * E_) return;
    int b = idx >> 11, e = idx & 2047;
    int h = e >> 7, d = e & 127;
    float acc = 0.f;
    #pragma unroll
    for (int ls = 0; ls < 8; ++ls)
        acc += g_opart[((ls * B_ + b) * H_ + h) * HD_ + d];
    g_o[idx] = acc;
}

// --------------------------------------------------------------------------------
extern "C" void kernel_launch(void* const* d_in, const int* in_sizes, int n_in,
                              void* d_out, int out_size) {
    const float* x    = (const float*)d_in[0];
    const float* ckv  = (const float*)d_in[1];
    const float* krc  = (const float*)d_in[2];
    const float* Wdq  = (const float*)d_in[3];
    const float* Wuq  = (const float*)d_in[4];
    const float* Wqr  = (const float*)d_in[5];
    const float* Wdkv = (const float*)d_in[6];
    const float* Wkr  = (const float*)d_in[7];
    const float* FU   = (const float*)d_in[8];
    const float* Wo   = (const float*)d_in[9];
    float* out = (float*)d_out;

    float *pCq, *pQc, *pPart, *pQrp, *pCkvn, *pKrn, *pO;
    cudaGetSymbolAddress((void**)&pCq,   g_Cq);
    cudaGetSymbolAddress((void**)&pQc,   g_Qc);
    cudaGetSymbolAddress((void**)&pPart, g_part);
    cudaGetSymbolAddress((void**)&pQrp,  g_qr_pre);
    cudaGetSymbolAddress((void**)&pCkvn, g_ckv_new);
    cudaGetSymbolAddress((void**)&pKrn,  g_kr_new);
    cudaGetSymbolAddress((void**)&pO,    g_o);

    k_invf<<<1, 64>>>();
    k_rope<<<(S_ * 64) / 256, 256>>>();

    auto gemm = [&](const float* X, const float* W, float* ob, int N) {
        int N4 = N >> 2;
        int thr = N4 < 256 ? N4 : 256;
        int gx = (N4 + thr - 1) / thr;
        k_gemm8v<<<dim3(gx, KS_), thr>>>(X, W, pPart, N);
        k_reduce8<<<(B_ * N + 255) / 256, 256>>>(pPart, ob, N);
    };

    gemm(x,   Wdq,  pCq,   E_);     // Cq = x @ Wdq
    gemm(x,   Wdkv, pCkvn, LOW_);   // ckv_new
    gemm(x,   Wkr,  pKrn,  HD_);    // kr_new
    gemm(pCq, Wuq,  pQc,   E_);     // Qc
    gemm(pCq, Wqr,  pQrp,  HD_);    // qr_pre
    k_ropeq<<<B_, 64>>>();

    k_qabs<<<dim3(64, 16), 256>>>(FU);
    k_scr<<<4096, 256>>>(krc);
    k_attn<<<dim3(SPLITS_, B_), 512>>>(ckv);
    k_combine<<<128, 512>>>();
    k_vproj<<<dim3(16, 8), 128>>>(FU);
    k_reduceo<<<(B_ * E_ + 255) / 256, 256>>>();

    gemm(pO, Wo, out, E_);          // out = o @ Wo
    (void)in_sizes; (void)n_in; (void)out_size;
}

// round 10
// speedup vs baseline: 1.3064x; 1.0189x over previous
#include <cuda_runtime.h>
#include <math.h>

#define B_ 8
#define E_ 2048
#define H_ 16
#define HD_ 128
#define LOW_ 512
#define SPREV_ 4095
#define S_ 4096
#define SPLITS_ 16
#define CHUNK_ 256
#define TS_ 16
#define NT_ (CHUNK_ / TS_)

__device__ float g_Cq[B_*E_];
__device__ float g_Qc[B_*E_];
__device__ float g_qr_pre[B_*HD_];
__device__ float g_qr[B_*HD_];
__device__ float g_qabs[B_*H_*LOW_];
__device__ float g_ckv_new[B_*LOW_];
__device__ float g_kr_new[B_*HD_];
__device__ float g_invf[64];
__device__ float g_cos[S_*64];
__device__ float g_sin[S_*64];
__device__ float g_scr[B_*S_];
__device__ float g_part[16*B_*E_];
__device__ unsigned g_cnt[16];           // zero-init; each gemm resets after use
__device__ float g_m[B_*H_*SPLITS_];
__device__ float g_l[B_*H_*SPLITS_];
__device__ float g_ctxp[B_*H_*SPLITS_*LOW_];
__device__ float g_opart[8*B_*H_*HD_];
__device__ float g_o[B_*E_];

__device__ __forceinline__ void fma2(float2& c, float2 a, float2 b) {
    unsigned long long C, A, Bv;
    C = *reinterpret_cast<unsigned long long*>(&c);
    A = *reinterpret_cast<unsigned long long*>(&a);
    Bv = *reinterpret_cast<unsigned long long*>(&b);
    asm("fma.rn.f32x2 %0, %1, %2, %0;" : "+l"(C) : "l"(A), "l"(Bv));
    c = *reinterpret_cast<float2*>(&C);
}

// ---------------- rope tables ---------------------------------------------------
__global__ void k_invf() {
    int i = threadIdx.x;  // 64
    g_invf[i] = (float)(1.0 / pow(10000.0, (double)i / 64.0));
}
__global__ void k_rope() {
    int idx = blockIdx.x * blockDim.x + threadIdx.x;
    if (idx >= S_ * 64) return;
    int s = idx >> 6, i = idx & 63;
    float ang = (float)s * g_invf[i];    // fp32 round like jnp
    float sn, c;
    sincosf(ang, &sn, &c);
    g_cos[idx] = c;
    g_sin[idx] = sn;
}

// ---------------- M=8 GEMM, fused deterministic cross-block reduction -----------
// Out[b,n] = sum_k X[b,k]*W[k,n], K=2048.
// grid (N4/NB4, KSY), 256 threads. NB4*KSUB == 256.
template<int NB4, int KSUB, int KSY>
__global__ void __launch_bounds__(256) k_gemmF(const float* __restrict__ X,
        const float* __restrict__ W, float* __restrict__ out, int N) {
    constexpr int KCH = E_ / (KSY * KSUB);      // k-iters per thread
    constexpr int KSLICE = KSUB * KCH;          // k-range per block
    __shared__ float xsm[B_][KSLICE];
    __shared__ float4 red[256][B_];
    __shared__ unsigned s_last;

    int tid = threadIdx.x;
    int n4l = tid % NB4;
    int ksub = tid / NB4;
    int N4 = N >> 2;
    int n4 = blockIdx.x * NB4 + n4l;
    int kblk = blockIdx.y * KSLICE;

    for (int i = tid; i < B_ * KSLICE; i += 256) {
        int bb = i / KSLICE, kk = i - bb * KSLICE;
        xsm[bb][kk] = X[bb * E_ + kblk + kk];
    }
    __syncthreads();

    const float4* Wp = (const float4*)W + (size_t)(kblk + ksub * KCH) * N4 + n4;
    float4 acc[B_];
    #pragma unroll
    for (int b = 0; b < B_; ++b) acc[b] = make_float4(0.f, 0.f, 0.f, 0.f);
    #pragma unroll
    for (int kk = 0; kk < KCH; ++kk) {
        float4 w4 = Wp[(size_t)kk * N4];
        #pragma unroll
        for (int b = 0; b < B_; ++b) {
            float xv = xsm[b][ksub * KCH + kk];
            acc[b].x = fmaf(xv, w4.x, acc[b].x);
            acc[b].y = fmaf(xv, w4.y, acc[b].y);
            acc[b].z = fmaf(xv, w4.z, acc[b].z);
            acc[b].w = fmaf(xv, w4.w, acc[b].w);
        }
    }
    #pragma unroll
    for (int b = 0; b < B_; ++b) red[tid][b] = acc[b];
    __syncthreads();

    // in-block reduce across KSUB (fixed order) + write partial
    for (int p = tid; p < NB4 * B_; p += 256) {
        int b = p / NB4, nl = p - b * NB4;
        float4 s = red[nl][b];
        #pragma unroll
        for (int ks = 1; ks < KSUB; ++ks) {
            float4 t = red[ks * NB4 + nl][b];
            s.x += t.x; s.y += t.y; s.z += t.z; s.w += t.w;
        }
        ((float4*)g_part)[(size_t)blockIdx.y * (B_ * N4) + (size_t)b * N4
                          + blockIdx.x * NB4 + nl] = s;
    }
    __threadfence();
    if (tid == 0) {
        unsigned old = atomicAdd(&g_cnt[blockIdx.x], 1u);
        s_last = (old == KSY - 1) ? 1u : 0u;
        if (s_last) g_cnt[blockIdx.x] = 0u;   // reset for graph replay
    }
    __syncthreads();
    if (!s_last) return;

    // last block: sum KSY partials in fixed order
    for (int p = tid; p < NB4 * B_; p += 256) {
        int b = p / NB4, nl = p - b * NB4;
        size_t base = (size_t)b * N4 + blockIdx.x * NB4 + nl;
        float4 s = ((const float4*)g_part)[base];
        #pragma unroll 4
        for (int ky = 1; ky < KSY; ++ky) {
            float4 t = ((const float4*)g_part)[(size_t)ky * (B_ * N4) + base];
            s.x += t.x; s.y += t.y; s.z += t.z; s.w += t.w;
        }
        ((float4*)out)[base] = s;
    }
}

// ---------------- rope query at pos S-1 -----------------------------------------
__global__ void k_ropeq() {
    int b = blockIdx.x, i = threadIdx.x;   // 64
    float q1 = g_qr_pre[b * HD_ + i];
    float q2 = g_qr_pre[b * HD_ + i + 64];
    float c = g_cos[(S_ - 1) * 64 + i];
    float s = g_sin[(S_ - 1) * 64 + i];
    g_qr[b * HD_ + i]      = q1 * c - q2 * s;
    g_qr[b * HD_ + i + 64] = q1 * s + q2 * c;
}

// ---------------- absorbed query ------------------------------------------------
__global__ void k_qabs(const float* __restrict__ FU) {
    int h = blockIdx.y;
    int w = threadIdx.x >> 5, lane = threadIdx.x & 31;
    int low = blockIdx.x * 8 + w;
    float4 w4 = *(const float4*)(FU + (size_t)low * (2 * E_) + h * HD_ + lane * 4);
    #pragma unroll
    for (int b = 0; b < B_; ++b) {
        float4 q4 = *(const float4*)(g_Qc + b * E_ + h * HD_ + lane * 4);
        float acc = w4.x * q4.x + w4.y * q4.y + w4.z * q4.z + w4.w * q4.w;
        #pragma unroll
        for (int off = 16; off; off >>= 1) acc += __shfl_xor_sync(0xffffffffu, acc, off);
        if (lane == 0) g_qabs[(b * H_ + h) * LOW_ + low] = acc;
    }
}

// ---------------- rotary scores -------------------------------------------------
__global__ void k_scr(const float* __restrict__ krc) {
    int gw = blockIdx.x * 8 + (threadIdx.x >> 5);
    int lane = threadIdx.x & 31;
    int b = gw >> 12;
    int s = gw & (S_ - 1);
    const float* kr = (s < SPREV_) ? (krc + ((size_t)b * SPREV_ + s) * HD_)
                                   : (g_kr_new + b * HD_);
    float k1a = kr[lane], k1b = kr[lane + 32], k2a = kr[lane + 64], k2b = kr[lane + 96];
    float ca = g_cos[s * 64 + lane], cb = g_cos[s * 64 + lane + 32];
    float sa = g_sin[s * 64 + lane], sb = g_sin[s * 64 + lane + 32];
    const float* q = g_qr + b * HD_;
    float q1a = q[lane], q1b = q[lane + 32], q2a = q[lane + 64], q2b = q[lane + 96];
    float acc = ca * (q1a * k1a + q2a * k2a) + sa * (q2a * k1a - q1a * k2a)
              + cb * (q1b * k1b + q2b * k2b) + sb * (q2b * k1b - q1b * k2b);
    #pragma unroll
    for (int off = 16; off; off >>= 1) acc += __shfl_xor_sync(0xffffffffu, acc, off);
    if (lane == 0) g_scr[b * S_ + s] = acc;
}

// ---------------- flash attention: prefetch + f32x2 -----------------------------
__global__ void __launch_bounds__(512, 1) k_attn(const float* __restrict__ ckv) {
    __shared__ float cvs[TS_][LOW_];
    __shared__ float p_s[TS_][20];
    __shared__ float alpha_s[20];
    __shared__ float scs[CHUNK_];
    int split = blockIdx.x, b = blockIdx.y;
    int tid = threadIdx.x, w = tid >> 5, lane = tid & 31;
    int s0 = split * CHUNK_;

    if (tid < CHUNK_) scs[tid] = g_scr[b * S_ + s0 + tid];

    float2 q2[8];
    {
        const float* qa = g_qabs + (b * H_ + w) * LOW_;
        #pragma unroll
        for (int g = 0; g < 4; ++g) {
            float4 t = *(const float4*)(qa + g * 128 + lane * 4);
            q2[2 * g]     = make_float2(t.x, t.y);
            q2[2 * g + 1] = make_float2(t.z, t.w);
        }
    }
    float m = -1e30f, l = 0.f;
    float2 ctx2[8];
    #pragma unroll
    for (int hp = 0; hp < 8; ++hp) ctx2[hp] = make_float2(0.f, 0.f);

    int ldr = tid >> 7;
    int ldc = (tid & 127) << 2;
    float4 pf[4];

    #pragma unroll
    for (int i = 0; i < 4; ++i) {
        int sidx = s0 + ldr + 4 * i;
        const float* src = (sidx < SPREV_)
            ? (ckv + ((size_t)b * SPREV_ + sidx) * LOW_ + ldc)
            : (g_ckv_new + b * LOW_ + ldc);
        pf[i] = *(const float4*)src;
    }
    #pragma unroll
    for (int i = 0; i < 4; ++i) *(float4*)&cvs[ldr + 4 * i][ldc] = pf[i];
    __syncthreads();

    for (int tile = 0; tile < NT_; ++tile) {
        int sb = s0 + tile * TS_;
        if (tile + 1 < NT_) {
            #pragma unroll
            for (int i = 0; i < 4; ++i) {
                int sidx = sb + TS_ + ldr + 4 * i;
                const float* src = (sidx < SPREV_)
                    ? (ckv + ((size_t)b * SPREV_ + sidx) * LOW_ + ldc)
                    : (g_ckv_new + b * LOW_ + ldc);
                pf[i] = *(const float4*)src;
            }
        }

        float sc[TS_];
        #pragma unroll
        for (int r = 0; r < TS_; ++r) {
            float2 a2 = make_float2(0.f, 0.f);
            #pragma unroll
            for (int g = 0; g < 4; ++g) {
                float4 c = *(const float4*)&cvs[r][g * 128 + lane * 4];
                fma2(a2, make_float2(c.x, c.y), q2[2 * g]);
                fma2(a2, make_float2(c.z, c.w), q2[2 * g + 1]);
            }
            float acc = a2.x + a2.y;
            #pragma unroll
            for (int off = 16; off; off >>= 1) acc += __shfl_xor_sync(0xffffffffu, acc, off);
            sc[r] = acc;
        }
        float mt = -1e30f;
        #pragma unroll
        for (int r = 0; r < TS_; ++r) {
            sc[r] = (sc[r] + scs[tile * TS_ + r]) * 0.0625f;
            mt = fmaxf(mt, sc[r]);
        }
        float mn = fmaxf(m, mt);
        float al = __expf(m - mn);
        float ps = 0.f;
        float p[TS_];
        #pragma unroll
        for (int r = 0; r < TS_; ++r) { p[r] = __expf(sc[r] - mn); ps += p[r]; }
        l = l * al + ps;
        m = mn;
        if (lane == 0) {
            alpha_s[w] = al;
            #pragma unroll
            for (int r = 0; r < TS_; ++r) p_s[r][w] = p[r];
        }
        __syncthreads();

        float cv[TS_];
        #pragma unroll
        for (int r = 0; r < TS_; ++r) cv[r] = cvs[r][tid];
        #pragma unroll
        for (int hp = 0; hp < 8; ++hp) {
            float2 alp = *(const float2*)&alpha_s[2 * hp];
            ctx2[hp].x *= alp.x;
            ctx2[hp].y *= alp.y;
        }
        #pragma unroll
        for (int r = 0; r < TS_; ++r) {
            float2 cvr = make_float2(cv[r], cv[r]);
            #pragma unroll
            for (int g = 0; g < 4; ++g) {
                float4 pq = *(const float4*)&p_s[r][4 * g];
                fma2(ctx2[2 * g],     cvr, make_float2(pq.x, pq.y));
                fma2(ctx2[2 * g + 1], cvr, make_float2(pq.z, pq.w));
            }
        }
        __syncthreads();

        if (tile + 1 < NT_) {
            #pragma unroll
            for (int i = 0; i < 4; ++i) *(float4*)&cvs[ldr + 4 * i][ldc] = pf[i];
            __syncthreads();
        }
    }

    #pragma unroll
    for (int hp = 0; hp < 8; ++hp) {
        g_ctxp[(size_t)((b * H_ + 2 * hp)     * SPLITS_ + split) * LOW_ + tid] = ctx2[hp].x;
        g_ctxp[(size_t)((b * H_ + 2 * hp + 1) * SPLITS_ + split) * LOW_ + tid] = ctx2[hp].y;
    }
    if (lane == 0) {
        g_m[(b * H_ + w) * SPLITS_ + split] = m;
        g_l[(b * H_ + w) * SPLITS_ + split] = l;
    }
}

// ---------------- fused combine + V projection ----------------------------------
__global__ void k_vprojC(const float* __restrict__ FU) {
    int h = blockIdx.x, ls = blockIdx.y;   // 16 x 8
    int d = threadIdx.x;                   // 128
    __shared__ float cf[B_][64];
    #pragma unroll
    for (int j = 0; j < 4; ++j) {
        int i = d + 128 * j;
        int bb = i >> 6, lo = i & 63;
        int bh = bb * H_ + h;
        float mg = -1e30f;
        #pragma unroll
        for (int s = 0; s < SPLITS_; ++s) mg = fmaxf(mg, g_m[bh * SPLITS_ + s]);
        float L = 0.f, acc = 0.f;
        #pragma unroll
        for (int s = 0; s < SPLITS_; ++s) {
            float wgt = __expf(g_m[bh * SPLITS_ + s] - mg);
            L += g_l[bh * SPLITS_ + s] * wgt;
            acc += g_ctxp[(size_t)(bh * SPLITS_ + s) * LOW_ + ls * 64 + lo] * wgt;
        }
        cf[bb][lo] = acc / L;
    }
    __syncthreads();
    float acc[B_] = {0.f,0.f,0.f,0.f,0.f,0.f,0.f,0.f};
    #pragma unroll 8
    for (int lo = 0; lo < 64; ++lo) {
        float wv = FU[(size_t)(ls * 64 + lo) * (2 * E_) + E_ + h * HD_ + d];
        #pragma unroll
        for (int b = 0; b < B_; ++b) acc[b] = fmaf(cf[b][lo], wv, acc[b]);
    }
    #pragma unroll
    for (int b = 0; b < B_; ++b)
        g_opart[((ls * B_ + b) * H_ + h) * HD_ + d] = acc[b];
}

__global__ void k_reduceo() {
    int idx = blockIdx.x * 256 + threadIdx.x;
    if (idx >= B_ * E_) return;
    int b = idx >> 11, e = idx & 2047;
    int h = e >> 7, d = e & 127;
    float acc = 0.f;
    #pragma unroll
    for (int ls = 0; ls < 8; ++ls)
        acc += g_opart[((ls * B_ + b) * H_ + h) * HD_ + d];
    g_o[idx] = acc;
}

// --------------------------------------------------------------------------------
extern "C" void kernel_launch(void* const* d_in, const int* in_sizes, int n_in,
                              void* d_out, int out_size) {
    const float* x    = (const float*)d_in[0];
    const float* ckv  = (const float*)d_in[1];
    const float* krc  = (const float*)d_in[2];
    const float* Wdq  = (const float*)d_in[3];
    const float* Wuq  = (const float*)d_in[4];
    const float* Wqr  = (const float*)d_in[5];
    const float* Wdkv = (const float*)d_in[6];
    const float* Wkr  = (const float*)d_in[7];
    const float* FU   = (const float*)d_in[8];
    const float* Wo   = (const float*)d_in[9];
    float* out = (float*)d_out;

    float *pCq, *pQc, *pQrp, *pCkvn, *pKrn, *pO;
    cudaGetSymbolAddress((void**)&pCq,   g_Cq);
    cudaGetSymbolAddress((void**)&pQc,   g_Qc);
    cudaGetSymbolAddress((void**)&pQrp,  g_qr_pre);
    cudaGetSymbolAddress((void**)&pCkvn, g_ckv_new);
    cudaGetSymbolAddress((void**)&pKrn,  g_kr_new);
    cudaGetSymbolAddress((void**)&pO,    g_o);

    // launch order puts the Wuq E-GEMM at slot 6 (ncu -s 5 -c 1 target)
    k_invf<<<1, 64>>>();                                         // 1
    k_rope<<<(S_ * 64) / 256, 256>>>();                          // 2
    k_gemmF<64,4,16><<<dim3(8, 16), 256>>>(x, Wdq, pCq, E_);     // 3
    k_gemmF<64,4,16><<<dim3(2, 16), 256>>>(x, Wdkv, pCkvn, LOW_);// 4
    k_gemmF<32,8,16><<<dim3(1, 16), 256>>>(x, Wkr, pKrn, HD_);   // 5
    k_gemmF<64,4,16><<<dim3(8, 16), 256>>>(pCq, Wuq, pQc, E_);   // 6  <- profiled
    k_gemmF<32,8,16><<<dim3(1, 16), 256>>>(pCq, Wqr, pQrp, HD_); // 7
    k_ropeq<<<B_, 64>>>();                                       // 8
    k_qabs<<<dim3(64, 16), 256>>>(FU);                           // 9
    k_scr<<<4096, 256>>>(krc);                                   // 10
    k_attn<<<dim3(SPLITS_, B_), 512>>>(ckv);                     // 11
    k_vprojC<<<dim3(16, 8), 128>>>(FU);                          // 12
    k_reduceo<<<(B_ * E_ + 255) / 256, 256>>>();                 // 13
    k_gemmF<64,4,16><<<dim3(8, 16), 256>>>(pO, Wo, out, E_);     // 14
    (void)in_sizes; (void)n_in; (void)out_size;
}